// round 7
// baseline (speedup 1.0000x reference)
#include <cuda_runtime.h>
#include <cuda_bf16.h>

// Problem constants (fixed by setup_inputs)
#define C_DOWN 256
#define C_UP   128
#define C_OUT  128
#define N_DOWN 16384

#define TM 32          // rows per block
#define KT 32          // K tile
#define THREADS 256

__global__ void __launch_bounds__(THREADS)
fused_upsample_mlp(const float* __restrict__ x_down,
                   const float* __restrict__ x_up,
                   const int* __restrict__ up_idx,     // JAX x64 disabled -> int32!
                   const float* __restrict__ W_lin,
                   const float* __restrict__ b_lin,
                   const float* __restrict__ W_fus,
                   const float* __restrict__ b_fus,
                   float* __restrict__ out,
                   long long n_up_per_batch)
{
    __shared__ float Xs[TM][36];          // K-tile of activations (pad for vec4 + banks)
    __shared__ float Ws[KT][128];         // K-tile of weights
    __shared__ float Hs[TM][C_UP];        // hidden (x_lin) for this row tile
    __shared__ long long gbase[TM];       // gathered x_down row base offsets

    const int tid = threadIdx.x;
    const long long p0 = (long long)blockIdx.x * TM;

    if (tid < TM) {
        long long p = p0 + tid;
        long long b = p / n_up_per_batch;
        long long r = (long long)up_idx[p];
        gbase[tid] = (b * N_DOWN + r) * C_DOWN;
    }
    __syncthreads();

    const int tm = tid >> 4;       // 0..15 -> 2 rows each
    const int tn = tid & 15;       // 0..15 -> 8 cols each
    const int row0 = tm * 2;
    const int col0 = tn * 8;

    float acc[2][8];
#pragma unroll
    for (int i = 0; i < 2; i++)
#pragma unroll
        for (int j = 0; j < 8; j++) acc[i][j] = 0.f;

    // ---------------- Stage A: hidden = leaky(Xg @ W_lin + b_lin) ----------------
    for (int kt = 0; kt < C_DOWN / KT; kt++) {
        // Xs: 32 rows x 32 cols, one float4 per thread (gathered rows, coalesced 128B/row)
        {
            const int i  = tid * 4;
            const int r  = i >> 5;
            const int kk = i & 31;
            float4 v = *reinterpret_cast<const float4*>(&x_down[gbase[r] + kt * KT + kk]);
            *reinterpret_cast<float4*>(&Xs[r][kk]) = v;
        }
        // Ws: 32 x 128, 4 float4 per thread, lane-contiguous
#pragma unroll
        for (int u = 0; u < 4; u++) {
            const int i  = u * 1024 + tid * 4;
            const int kr = i >> 7;
            const int c  = i & 127;
            *reinterpret_cast<float4*>(&Ws[kr][c]) =
                *reinterpret_cast<const float4*>(&W_lin[(kt * KT + kr) * 128 + c]);
        }
        __syncthreads();

#pragma unroll
        for (int k = 0; k < KT; k++) {
            const float a0 = Xs[row0][k];
            const float a1 = Xs[row0 + 1][k];
            const float4 w0 = *reinterpret_cast<const float4*>(&Ws[k][col0]);
            const float4 w1 = *reinterpret_cast<const float4*>(&Ws[k][col0 + 4]);
            acc[0][0] += a0 * w0.x; acc[0][1] += a0 * w0.y;
            acc[0][2] += a0 * w0.z; acc[0][3] += a0 * w0.w;
            acc[0][4] += a0 * w1.x; acc[0][5] += a0 * w1.y;
            acc[0][6] += a0 * w1.z; acc[0][7] += a0 * w1.w;
            acc[1][0] += a1 * w0.x; acc[1][1] += a1 * w0.y;
            acc[1][2] += a1 * w0.z; acc[1][3] += a1 * w0.w;
            acc[1][4] += a1 * w1.x; acc[1][5] += a1 * w1.y;
            acc[1][6] += a1 * w1.z; acc[1][7] += a1 * w1.w;
        }
        __syncthreads();
    }

    // Epilogue A: bias + leaky, stash into Hs, reset acc
#pragma unroll
    for (int i = 0; i < 2; i++)
#pragma unroll
        for (int j = 0; j < 8; j++) {
            float v = acc[i][j] + b_lin[col0 + j];
            v = (v >= 0.f) ? v : 0.1f * v;
            Hs[row0 + i][col0 + j] = v;
            acc[i][j] = 0.f;
        }
    // No sync needed: Hs is first read at kt=4 of stage B, behind >=1 barrier.

    // ---------------- Stage B: out = leaky([x_up, hidden] @ W_fus + b_fus) -------
    const float* xup_base = x_up + p0 * C_UP;
    for (int kt = 0; kt < (2 * C_UP) / KT; kt++) {
        {
            const int i  = tid * 4;
            const int r  = i >> 5;
            const int kk = i & 31;
            if (kt < C_UP / KT) {
                *reinterpret_cast<float4*>(&Xs[r][kk]) =
                    *reinterpret_cast<const float4*>(&xup_base[(long long)r * C_UP + kt * KT + kk]);
            } else {
                *reinterpret_cast<float4*>(&Xs[r][kk]) =
                    *reinterpret_cast<const float4*>(&Hs[r][(kt - C_UP / KT) * KT + kk]);
            }
        }
#pragma unroll
        for (int u = 0; u < 4; u++) {
            const int i  = u * 1024 + tid * 4;
            const int kr = i >> 7;
            const int c  = i & 127;
            *reinterpret_cast<float4*>(&Ws[kr][c]) =
                *reinterpret_cast<const float4*>(&W_fus[(kt * KT + kr) * 128 + c]);
        }
        __syncthreads();

#pragma unroll
        for (int k = 0; k < KT; k++) {
            const float a0 = Xs[row0][k];
            const float a1 = Xs[row0 + 1][k];
            const float4 w0 = *reinterpret_cast<const float4*>(&Ws[k][col0]);
            const float4 w1 = *reinterpret_cast<const float4*>(&Ws[k][col0 + 4]);
            acc[0][0] += a0 * w0.x; acc[0][1] += a0 * w0.y;
            acc[0][2] += a0 * w0.z; acc[0][3] += a0 * w0.w;
            acc[0][4] += a0 * w1.x; acc[0][5] += a0 * w1.y;
            acc[0][6] += a0 * w1.z; acc[0][7] += a0 * w1.w;
            acc[1][0] += a1 * w0.x; acc[1][1] += a1 * w0.y;
            acc[1][2] += a1 * w0.z; acc[1][3] += a1 * w0.w;
            acc[1][4] += a1 * w1.x; acc[1][5] += a1 * w1.y;
            acc[1][6] += a1 * w1.z; acc[1][7] += a1 * w1.w;
        }
        __syncthreads();
    }

    // Epilogue B: bias + leaky -> global (float4 stores)
    float* obase = out + p0 * C_OUT;
#pragma unroll
    for (int i = 0; i < 2; i++) {
        float v[8];
#pragma unroll
        for (int j = 0; j < 8; j++) {
            float t = acc[i][j] + b_fus[col0 + j];
            v[j] = (t >= 0.f) ? t : 0.1f * t;
        }
        float4* dst = reinterpret_cast<float4*>(&obase[(long long)(row0 + i) * C_OUT + col0]);
        dst[0] = make_float4(v[0], v[1], v[2], v[3]);
        dst[1] = make_float4(v[4], v[5], v[6], v[7]);
    }
}

extern "C" void kernel_launch(void* const* d_in, const int* in_sizes, int n_in,
                              void* d_out, int out_size)
{
    const float* x_down = (const float*)d_in[0];
    const float* x_up   = (const float*)d_in[1];
    const int*   up_idx = (const int*)d_in[2];      // int32 (JAX x64 off)
    const float* W_lin  = (const float*)d_in[3];
    const float* b_lin  = (const float*)d_in[4];
    const float* W_fus  = (const float*)d_in[5];
    const float* b_fus  = (const float*)d_in[6];
    float*       out    = (float*)d_out;

    const long long total_rows = in_sizes[2];                         // B * N_up
    const long long B          = (long long)in_sizes[0] / ((long long)N_DOWN * C_DOWN);
    const long long n_up_pb    = total_rows / B;

    const int grid = (int)((total_rows + TM - 1) / TM);
    fused_upsample_mlp<<<grid, THREADS>>>(x_down, x_up, up_idx,
                                          W_lin, b_lin, W_fus, b_fus,
                                          out, n_up_pb);
}

// round 12
// speedup vs baseline: 4.4246x; 4.4246x over previous
#include <cuda_runtime.h>
#include <cuda_bf16.h>
#include <cstdint>

// ---------------------------------------------------------------------------
// Fused Upsampling MLP via warp-level HMMA (mma.sync m16n8k16 bf16, fp32 acc),
// bf16x3 split (hi*hi + lo*hi + hi*lo) for fp32-level accuracy.
// NOTE: harness compiles PTX at target sm_103 (no 'a') -> tcgen05/TMEM/mbarrier
// unavailable; everything here is baseline ISA (ldmatrix sm_75+, mma sm_80+).
//   Stage A: H = leaky( gather(x_down) @ W_lin + b_lin )   [K=256 -> N=128]
//   Stage B: O = leaky( [x_up, H] @ W_fus + b_fus )        [K=256 -> N=128]
// Per CTA: M=128 rows, N=128, K in 4 chunks of 64.
// 8 warps = 4(M) x 2(N); warp tile 32x64 = 2x8 m16n8k16 tiles.
// ---------------------------------------------------------------------------

#define C_DOWN 256
#define C_UP   128
#define N_DOWN 16384
#define TMROWS 128
#define THREADS 256

// smem layout (all regions 1024B-aligned for SW128 swizzle)
#define SM_GB    0                       // 128 x int64 gather bases (1KB)
#define SM_A_HI  1024
#define SM_A_LO  (SM_A_HI + 16384)       // A chunk: [128 rows][64 k] bf16, 128B rows
#define SM_B     (SM_A_LO + 16384)       // B chunk blob: [hi: half0 8KB, half1 8KB][lo: same]
#define SM_H     (SM_B + 32768)          // H: 2 chunks x (hi 16KB + lo 16KB)
#define SMEM_TOTAL (SM_H + 65536)        // 132096 B

#define SWZ(o) ((o) ^ (((o) >> 3) & 0x70))

// Pre-split, pre-swizzled weights. Per chunk c (64 K): [hi: n-half0, n-half1][lo: ...]
// Each half tile: [64 k][64 n] bf16, 128B rows, SW128.
__device__ __align__(1024) unsigned char g_wlin[131072];
__device__ __align__(1024) unsigned char g_wfus[131072];

// ------------------------------- helpers -----------------------------------
__device__ __forceinline__ uint32_t smem_u32(const void* p) {
    uint32_t a;
    asm("{ .reg .u64 t; cvta.to.shared.u64 t, %1; cvt.u32.u64 %0, t; }"
        : "=r"(a) : "l"(p));
    return a;
}
__device__ __forceinline__ void ldsm4(uint32_t* r, uint32_t a) {
    asm volatile("ldmatrix.sync.aligned.m8n8.x4.shared.b16 {%0,%1,%2,%3}, [%4];"
                 : "=r"(r[0]), "=r"(r[1]), "=r"(r[2]), "=r"(r[3]) : "r"(a));
}
__device__ __forceinline__ void ldsm2t(uint32_t* r, uint32_t a) {
    asm volatile("ldmatrix.sync.aligned.m8n8.x2.trans.shared.b16 {%0,%1}, [%2];"
                 : "=r"(r[0]), "=r"(r[1]) : "r"(a));
}
__device__ __forceinline__ void mma_bf16(float* d, const uint32_t* a, const uint32_t* b) {
    asm volatile("mma.sync.aligned.m16n8k16.row.col.f32.bf16.bf16.f32 "
                 "{%0,%1,%2,%3},{%4,%5,%6,%7},{%8,%9},{%0,%1,%2,%3};"
                 : "+f"(d[0]), "+f"(d[1]), "+f"(d[2]), "+f"(d[3])
                 : "r"(a[0]), "r"(a[1]), "r"(a[2]), "r"(a[3]),
                   "r"(b[0]), "r"(b[1]));
}
// split fp32 pair -> packed bf16x2 hi and lo
__device__ __forceinline__ uint32_t split2(float a, float b, uint32_t& lo_out) {
    __nv_bfloat16 ha = __float2bfloat16(a), hb = __float2bfloat16(b);
    __nv_bfloat16 la = __float2bfloat16(a - __bfloat162float(ha));
    __nv_bfloat16 lb = __float2bfloat16(b - __bfloat162float(hb));
    lo_out = ((uint32_t)__bfloat16_as_ushort(lb) << 16) | __bfloat16_as_ushort(la);
    return ((uint32_t)__bfloat16_as_ushort(hb) << 16) | __bfloat16_as_ushort(ha);
}

// ----------------------------- weight pack kernel ---------------------------
__global__ void pack_w(const float* __restrict__ Wlin, const float* __restrict__ Wfus) {
    int i = blockIdx.x * blockDim.x + threadIdx.x;    // 0..32767 over [K=256][N=128]
    if (i >= 32768) return;
    int k = i >> 7, n = i & 127;
    int c = k >> 6, kk = k & 63;
    int half = n >> 6, nn = n & 63;
    uint32_t off = (uint32_t)kk * 128u + (uint32_t)nn * 2u;
    uint32_t sw = SWZ(off);
    uint32_t base = (uint32_t)c * 32768u + (uint32_t)half * 8192u;
    {
        float w = Wlin[i];
        __nv_bfloat16 hi = __float2bfloat16(w);
        __nv_bfloat16 lo = __float2bfloat16(w - __bfloat162float(hi));
        *(__nv_bfloat16*)(g_wlin + base + sw)         = hi;
        *(__nv_bfloat16*)(g_wlin + base + 16384 + sw) = lo;
    }
    {
        float w = Wfus[i];
        __nv_bfloat16 hi = __float2bfloat16(w);
        __nv_bfloat16 lo = __float2bfloat16(w - __bfloat162float(hi));
        *(__nv_bfloat16*)(g_wfus + base + sw)         = hi;
        *(__nv_bfloat16*)(g_wfus + base + 16384 + sw) = lo;
    }
}

// --------------------- per-chunk warp MMA (64 K-values) ---------------------
// acc[mt][nt][4]; aHi/aLo: bases of [128][64] bf16 SW128 tiles;
// bHi: base of this warp's 64x64 B-half (hi); bLo = bHi + 16384.
__device__ __forceinline__ void compute_chunk(float acc[2][8][4],
                                              uint32_t aHi, uint32_t aLo,
                                              uint32_t bHi, uint32_t bLo,
                                              int lane, int warpMrow)
{
    const uint32_t csel = (lane & 16) ? 16u : 0u;      // +8 bf16 k-cols for a2/a3
    const int arow = warpMrow + (lane & 15);
#pragma unroll
    for (int kb = 0; kb < 64; kb += 16) {
        uint32_t ah[2][4], al[2][4];
#pragma unroll
        for (int mt = 0; mt < 2; mt++) {
            uint32_t off = (uint32_t)(arow + mt * 16) * 128u + (uint32_t)kb * 2u + csel;
            uint32_t sw = SWZ(off);
            ldsm4(ah[mt], aHi + sw);
            ldsm4(al[mt], aLo + sw);
        }
        const uint32_t broff = (uint32_t)(kb + (lane & 15)) * 128u;
#pragma unroll
        for (int nt = 0; nt < 8; nt++) {
            uint32_t sw = SWZ(broff + (uint32_t)nt * 16u);
            uint32_t bh[2], bl[2];
            ldsm2t(bh, bHi + sw);
            ldsm2t(bl, bLo + sw);
#pragma unroll
            for (int mt = 0; mt < 2; mt++) {
                mma_bf16(acc[mt][nt], ah[mt], bh);   // hi*hi
                mma_bf16(acc[mt][nt], al[mt], bh);   // lo*hi
                mma_bf16(acc[mt][nt], ah[mt], bl);   // hi*lo
            }
        }
    }
}

// ------------------------------- main kernel --------------------------------
__global__ void __launch_bounds__(THREADS, 1)
mlp_tc_kernel(const float* __restrict__ x_down,
              const float* __restrict__ x_up,
              const int* __restrict__ up_idx,
              const float* __restrict__ b_lin,
              const float* __restrict__ b_fus,
              float* __restrict__ out,
              long long n_up_per_batch)
{
    extern __shared__ __align__(1024) char smem[];
    const uint32_t sb = smem_u32(smem);
    const int tid  = threadIdx.x;
    const int wid  = tid >> 5;
    const int lane = tid & 31;
    const int warp_m = wid & 3;      // 32-row slice
    const int warp_n = wid >> 2;     // 64-col slice
    const int warpMrow = warp_m * 32;
    const int gid = lane >> 2, tig = lane & 3;
    const long long p0 = (long long)blockIdx.x * TMROWS;

    long long* gbase = (long long*)(smem + SM_GB);
    if (tid < TMROWS) {
        long long p = p0 + tid;
        long long b = p / n_up_per_batch;
        gbase[tid] = (b * N_DOWN + (long long)up_idx[p]) * C_DOWN;
    }
    __syncthreads();

    const int row  = tid >> 1;   // 0..127 (fill row)
    const int half = tid & 1;    // which 32-float half of a 64-k chunk

    const uint32_t bHiW = sb + SM_B + (uint32_t)warp_n * 8192u;
    const uint32_t bLoW = bHiW + 16384u;

    float acc[2][8][4];
#pragma unroll
    for (int a = 0; a < 2; a++)
#pragma unroll
        for (int b = 0; b < 8; b++)
#pragma unroll
            for (int c = 0; c < 4; c++) acc[a][b][c] = 0.f;

    // =========================== STAGE A ===========================
    for (int c = 0; c < 4; c++) {
        if (c > 0) __syncthreads();   // protect smem reuse across chunks
        // A chunk: gathered x_down rows -> bf16 hi/lo, SW128
        {
            const float* src = x_down + gbase[row] + c * 64 + half * 32;
            const uint32_t rbase = (uint32_t)row * 128u + (uint32_t)half * 64u;
#pragma unroll
            for (int i = 0; i < 8; i++) {
                float4 v = *reinterpret_cast<const float4*>(src + i * 4);
                uint32_t lo0, lo1;
                uint32_t hi0 = split2(v.x, v.y, lo0);
                uint32_t hi1 = split2(v.z, v.w, lo1);
                uint32_t sw = SWZ(rbase + i * 8u);
                *(uint2*)(smem + SM_A_HI + sw) = make_uint2(hi0, hi1);
                *(uint2*)(smem + SM_A_LO + sw) = make_uint2(lo0, lo1);
            }
        }
        // B chunk: 32KB pre-swizzled blob
        {
            const float4* srcB = (const float4*)(g_wlin + c * 32768);
            float4* dstB = (float4*)(smem + SM_B);
#pragma unroll
            for (int u = 0; u < 8; u++) dstB[tid + u * 256] = srcB[tid + u * 256];
        }
        __syncthreads();

        compute_chunk(acc, sb + SM_A_HI, sb + SM_A_LO, bHiW, bLoW, lane, warpMrow);
    }
    __syncthreads();

    // Epilogue A: bias + leaky -> H tiles (bf16 hi/lo, SW128, same layout as A)
#pragma unroll
    for (int mt = 0; mt < 2; mt++)
#pragma unroll
        for (int nt = 0; nt < 8; nt++) {
            int col = warp_n * 64 + nt * 8 + 2 * tig;    // even
            int hc = col >> 6, kk = col & 63;
            float bb0 = b_lin[col], bb1 = b_lin[col + 1];
            unsigned char* hbase = (unsigned char*)smem + SM_H + hc * 32768;
#pragma unroll
            for (int rr = 0; rr < 2; rr++) {
                int r = warpMrow + mt * 16 + gid + rr * 8;
                float v0 = acc[mt][nt][rr * 2]     + bb0;
                float v1 = acc[mt][nt][rr * 2 + 1] + bb1;
                v0 = (v0 >= 0.f) ? v0 : 0.1f * v0;
                v1 = (v1 >= 0.f) ? v1 : 0.1f * v1;
                uint32_t sw = SWZ((uint32_t)r * 128u + (uint32_t)kk * 2u);
                uint32_t lo;
                uint32_t hi = split2(v0, v1, lo);
                *(uint32_t*)(hbase + sw)         = hi;
                *(uint32_t*)(hbase + 16384 + sw) = lo;
                acc[mt][nt][rr * 2]     = 0.f;
                acc[mt][nt][rr * 2 + 1] = 0.f;
            }
        }
    __syncthreads();

    // =========================== STAGE B ===========================
    for (int c = 0; c < 4; c++) {
        if (c > 0) __syncthreads();
        if (c < 2) {   // A chunk from x_up (fp32 -> hi/lo); chunks 2,3 read H directly
            const float* src = x_up + (p0 + row) * C_UP + c * 64 + half * 32;
            const uint32_t rbase = (uint32_t)row * 128u + (uint32_t)half * 64u;
#pragma unroll
            for (int i = 0; i < 8; i++) {
                float4 v = *reinterpret_cast<const float4*>(src + i * 4);
                uint32_t lo0, lo1;
                uint32_t hi0 = split2(v.x, v.y, lo0);
                uint32_t hi1 = split2(v.z, v.w, lo1);
                uint32_t sw = SWZ(rbase + i * 8u);
                *(uint2*)(smem + SM_A_HI + sw) = make_uint2(hi0, hi1);
                *(uint2*)(smem + SM_A_LO + sw) = make_uint2(lo0, lo1);
            }
        }
        {
            const float4* srcB = (const float4*)(g_wfus + c * 32768);
            float4* dstB = (float4*)(smem + SM_B);
#pragma unroll
            for (int u = 0; u < 8; u++) dstB[tid + u * 256] = srcB[tid + u * 256];
        }
        __syncthreads();

        uint32_t aHi = (c < 2) ? (sb + SM_A_HI) : (sb + SM_H + (c - 2) * 32768);
        uint32_t aLo = aHi + 16384u;
        compute_chunk(acc, aHi, aLo, bHiW, bLoW, lane, warpMrow);
    }

    // Epilogue B: bias + leaky -> out (fp32 pairs)
#pragma unroll
    for (int mt = 0; mt < 2; mt++)
#pragma unroll
        for (int nt = 0; nt < 8; nt++) {
            int col = warp_n * 64 + nt * 8 + 2 * tig;
            float bb0 = b_fus[col], bb1 = b_fus[col + 1];
#pragma unroll
            for (int rr = 0; rr < 2; rr++) {
                long long r = p0 + warpMrow + mt * 16 + gid + rr * 8;
                float v0 = acc[mt][nt][rr * 2]     + bb0;
                float v1 = acc[mt][nt][rr * 2 + 1] + bb1;
                v0 = (v0 >= 0.f) ? v0 : 0.1f * v0;
                v1 = (v1 >= 0.f) ? v1 : 0.1f * v1;
                *reinterpret_cast<float2*>(out + r * 128 + col) = make_float2(v0, v1);
            }
        }
}

// ------------------------------- launch -------------------------------------
extern "C" void kernel_launch(void* const* d_in, const int* in_sizes, int n_in,
                              void* d_out, int out_size)
{
    const float* x_down = (const float*)d_in[0];
    const float* x_up   = (const float*)d_in[1];
    const int*   up_idx = (const int*)d_in[2];      // int32 (JAX x64 off)
    const float* W_lin  = (const float*)d_in[3];
    const float* b_lin  = (const float*)d_in[4];
    const float* W_fus  = (const float*)d_in[5];
    const float* b_fus  = (const float*)d_in[6];
    float*       out    = (float*)d_out;

    const long long total_rows = in_sizes[2];                         // B * N_up
    const long long B          = (long long)in_sizes[0] / ((long long)N_DOWN * C_DOWN);
    const long long n_up_pb    = total_rows / B;

    cudaFuncSetAttribute(mlp_tc_kernel,
                         cudaFuncAttributeMaxDynamicSharedMemorySize, SMEM_TOTAL);

    pack_w<<<128, 256>>>(W_lin, W_fus);

    const int grid = (int)(total_rows / TMROWS);
    mlp_tc_kernel<<<grid, THREADS, SMEM_TOTAL>>>(x_down, x_up, up_idx,
                                                 b_lin, b_fus, out, n_up_pb);
}

// round 14
// speedup vs baseline: 4.8681x; 1.1002x over previous
#include <cuda_runtime.h>
#include <cuda_bf16.h>
#include <cstdint>

// ---------------------------------------------------------------------------
// Fused Upsampling MLP via warp-level HMMA (mma.sync m16n8k16 bf16, fp32 acc),
// bf16x3 split (hi*hi + lo*hi + hi*lo) for fp32-level accuracy.
// Round 13: cp.async double-buffered software pipeline — prefetch chunk ph+1
// (raw fp32 A + pre-split B weights) while computing chunk ph. 8 unified
// phases: 0-3 stage A (gathered x_down @ W_lin), 4-7 stage B ([x_up,H] @ W_fus,
// phases 6-7 consume H directly from smem).
// Baseline ISA only (harness PTX target is sm_103, no 'a'): ldmatrix, mma.sync,
// cp.async. No tcgen05/TMEM/mbarrier.
// ---------------------------------------------------------------------------

#define C_DOWN 256
#define C_UP   128
#define N_DOWN 16384
#define TMROWS 128
#define THREADS 256

// smem layout (all regions 1024B-aligned for SW128 swizzle)
#define SM_GB    0                        // 128 x int64 gather bases (1KB)
#define SM_RAW   1024                     // raw fp32 A staging, 2 bufs x 32KB
#define SM_A     (SM_RAW + 65536)         // A tiles: hi 16KB + lo 16KB (single)
#define SM_B     (SM_A + 32768)           // B blob, 2 bufs x 32KB
#define SM_H     (SM_B + 65536)           // H: 2 chunks x (hi 16KB + lo 16KB)
#define SMEM_TOTAL (SM_H + 65536)         // 230400 B (<= 227KB opt-in)

#define SWZ(o) ((o) ^ (((o) >> 3) & 0x70))

// Pre-split, pre-swizzled weights. Per chunk c (64 K): [hi: n-half0, n-half1][lo: ...]
// Each half tile: [64 k][64 n] bf16, 128B rows, SW128.
__device__ __align__(1024) unsigned char g_wlin[131072];
__device__ __align__(1024) unsigned char g_wfus[131072];

// ------------------------------- helpers -----------------------------------
__device__ __forceinline__ uint32_t smem_u32(const void* p) {
    uint32_t a;
    asm("{ .reg .u64 t; cvta.to.shared.u64 t, %1; cvt.u32.u64 %0, t; }"
        : "=r"(a) : "l"(p));
    return a;
}
__device__ __forceinline__ void cpasync16(uint32_t dst, const void* src) {
    asm volatile("cp.async.cg.shared.global [%0], [%1], 16;"
                 :: "r"(dst), "l"(src) : "memory");
}
__device__ __forceinline__ void cp_commit() {
    asm volatile("cp.async.commit_group;" ::: "memory");
}
template<int N> __device__ __forceinline__ void cp_wait() {
    asm volatile("cp.async.wait_group %0;" :: "n"(N) : "memory");
}
__device__ __forceinline__ void ldsm4(uint32_t* r, uint32_t a) {
    asm volatile("ldmatrix.sync.aligned.m8n8.x4.shared.b16 {%0,%1,%2,%3}, [%4];"
                 : "=r"(r[0]), "=r"(r[1]), "=r"(r[2]), "=r"(r[3]) : "r"(a));
}
__device__ __forceinline__ void ldsm2t(uint32_t* r, uint32_t a) {
    asm volatile("ldmatrix.sync.aligned.m8n8.x2.trans.shared.b16 {%0,%1}, [%2];"
                 : "=r"(r[0]), "=r"(r[1]) : "r"(a));
}
__device__ __forceinline__ void mma_bf16(float* d, const uint32_t* a, const uint32_t* b) {
    asm volatile("mma.sync.aligned.m16n8k16.row.col.f32.bf16.bf16.f32 "
                 "{%0,%1,%2,%3},{%4,%5,%6,%7},{%8,%9},{%0,%1,%2,%3};"
                 : "+f"(d[0]), "+f"(d[1]), "+f"(d[2]), "+f"(d[3])
                 : "r"(a[0]), "r"(a[1]), "r"(a[2]), "r"(a[3]),
                   "r"(b[0]), "r"(b[1]));
}
// split fp32 pair -> packed bf16x2 hi and lo
__device__ __forceinline__ uint32_t split2(float a, float b, uint32_t& lo_out) {
    __nv_bfloat16 ha = __float2bfloat16(a), hb = __float2bfloat16(b);
    __nv_bfloat16 la = __float2bfloat16(a - __bfloat162float(ha));
    __nv_bfloat16 lb = __float2bfloat16(b - __bfloat162float(hb));
    lo_out = ((uint32_t)__bfloat16_as_ushort(lb) << 16) | __bfloat16_as_ushort(la);
    return ((uint32_t)__bfloat16_as_ushort(hb) << 16) | __bfloat16_as_ushort(ha);
}

// ----------------------------- weight pack kernel ---------------------------
__global__ void pack_w(const float* __restrict__ Wlin, const float* __restrict__ Wfus) {
    int i = blockIdx.x * blockDim.x + threadIdx.x;    // 0..32767 over [K=256][N=128]
    if (i >= 32768) return;
    int k = i >> 7, n = i & 127;
    int c = k >> 6, kk = k & 63;
    int half = n >> 6, nn = n & 63;
    uint32_t sw = SWZ((uint32_t)kk * 128u + (uint32_t)nn * 2u);
    uint32_t base = (uint32_t)c * 32768u + (uint32_t)half * 8192u;
    {
        float w = Wlin[i];
        __nv_bfloat16 hi = __float2bfloat16(w);
        __nv_bfloat16 lo = __float2bfloat16(w - __bfloat162float(hi));
        *(__nv_bfloat16*)(g_wlin + base + sw)         = hi;
        *(__nv_bfloat16*)(g_wlin + base + 16384 + sw) = lo;
    }
    {
        float w = Wfus[i];
        __nv_bfloat16 hi = __float2bfloat16(w);
        __nv_bfloat16 lo = __float2bfloat16(w - __bfloat162float(hi));
        *(__nv_bfloat16*)(g_wfus + base + sw)         = hi;
        *(__nv_bfloat16*)(g_wfus + base + 16384 + sw) = lo;
    }
}

// --------------------- per-chunk warp MMA (64 K-values) ---------------------
__device__ __forceinline__ void compute_chunk(float acc[2][8][4],
                                              uint32_t aHi, uint32_t aLo,
                                              uint32_t bHi, uint32_t bLo,
                                              int lane, int warpMrow)
{
    const uint32_t csel = (lane & 16) ? 16u : 0u;
    const int arow = warpMrow + (lane & 15);
#pragma unroll
    for (int kb = 0; kb < 64; kb += 16) {
        uint32_t ah[2][4], al[2][4];
#pragma unroll
        for (int mt = 0; mt < 2; mt++) {
            uint32_t sw = SWZ((uint32_t)(arow + mt * 16) * 128u + (uint32_t)kb * 2u + csel);
            ldsm4(ah[mt], aHi + sw);
            ldsm4(al[mt], aLo + sw);
        }
        const uint32_t broff = (uint32_t)(kb + (lane & 15)) * 128u;
#pragma unroll
        for (int nt = 0; nt < 8; nt++) {
            uint32_t sw = SWZ(broff + (uint32_t)nt * 16u);
            uint32_t bh[2], bl[2];
            ldsm2t(bh, bHi + sw);
            ldsm2t(bl, bLo + sw);
#pragma unroll
            for (int mt = 0; mt < 2; mt++) {
                mma_bf16(acc[mt][nt], ah[mt], bh);   // hi*hi
                mma_bf16(acc[mt][nt], al[mt], bh);   // lo*hi
                mma_bf16(acc[mt][nt], ah[mt], bl);   // hi*lo
            }
        }
    }
}

// ------------------------------- main kernel --------------------------------
__global__ void __launch_bounds__(THREADS, 1)
mlp_tc_kernel(const float* __restrict__ x_down,
              const float* __restrict__ x_up,
              const int* __restrict__ up_idx,
              const float* __restrict__ b_lin,
              const float* __restrict__ b_fus,
              float* __restrict__ out,
              long long n_up_per_batch)
{
    extern __shared__ __align__(1024) char smem[];
    const uint32_t sb = smem_u32(smem);
    const int tid  = threadIdx.x;
    const int wid  = tid >> 5;
    const int lane = tid & 31;
    const int warp_m = wid & 3;
    const int warp_n = wid >> 2;
    const int warpMrow = warp_m * 32;
    const int gid = lane >> 2, tig = lane & 3;
    const long long p0 = (long long)blockIdx.x * TMROWS;

    long long* gbase = (long long*)(smem + SM_GB);
    if (tid < TMROWS) {
        long long p = p0 + tid;
        long long b = p / n_up_per_batch;
        gbase[tid] = (b * N_DOWN + (long long)up_idx[p]) * C_DOWN;
    }
    __syncthreads();   // gbase ready before any prefetch

    const int row  = tid >> 1;   // fill/convert row
    const int half = tid & 1;    // 32-float half of 64-k chunk

    float acc[2][8][4];
#pragma unroll
    for (int a = 0; a < 2; a++)
#pragma unroll
        for (int b = 0; b < 8; b++)
#pragma unroll
            for (int c = 0; c < 4; c++) acc[a][b][c] = 0.f;

    // ---- prefetch: raw fp32 A chunk (ph<6) + pre-split B blob -> buf ----
    auto prefetch = [&](int ph, int buf) {
        // B blob: 32KB = 2048 x 16B segs
        const unsigned char* wsrc = ((ph < 4) ? g_wlin : g_wfus) + (ph & 3) * 32768;
        const uint32_t bdst = sb + SM_B + (uint32_t)buf * 32768u;
#pragma unroll
        for (int u = 0; u < 8; u++) {
            int s = tid + u * 256;
            cpasync16(bdst + (uint32_t)s * 16u, wsrc + s * 16);
        }
        // raw A: 128 rows x 64 fp32 (256B/row) = 2048 x 16B segs
        if (ph < 6) {
            const int c = ph & 3;                 // 0-3 for stage A, 0-1 for stage B
            const uint32_t rdst = sb + SM_RAW + (uint32_t)buf * 32768u;
#pragma unroll
            for (int u = 0; u < 8; u++) {
                int s = tid + u * 256;
                int r = s >> 4, sg = s & 15;
                const float* src = (ph < 4)
                    ? (x_down + gbase[r] + c * 64 + sg * 4)
                    : (x_up + (p0 + r) * C_UP + c * 64 + sg * 4);
                cpasync16(rdst + (uint32_t)s * 16u, src);
            }
        }
    };

    prefetch(0, 0);
    cp_commit();

    for (int ph = 0; ph < 8; ph++) {
        const int buf = ph & 1;
        if (ph < 7) { prefetch(ph + 1, buf ^ 1); cp_commit(); }
        if (ph < 7) cp_wait<1>(); else cp_wait<0>();
        __syncthreads();                       // all of chunk ph's copies visible

        uint32_t aHi, aLo;
        if (ph < 6) {
            // convert raw fp32 -> bf16 hi/lo SW128 tiles (single A buffer)
            const float* raw = (const float*)(smem + SM_RAW + buf * 32768);
            const float* src = raw + row * 64 + half * 32;
            const uint32_t rbase = (uint32_t)row * 128u + (uint32_t)half * 64u;
#pragma unroll
            for (int i = 0; i < 8; i++) {
                float4 v = *reinterpret_cast<const float4*>(src + i * 4);
                uint32_t lo0, lo1;
                uint32_t hi0 = split2(v.x, v.y, lo0);
                uint32_t hi1 = split2(v.z, v.w, lo1);
                uint32_t sw = SWZ(rbase + i * 8u);
                *(uint2*)(smem + SM_A + sw)          = make_uint2(hi0, hi1);
                *(uint2*)(smem + SM_A + 16384 + sw)  = make_uint2(lo0, lo1);
            }
            __syncthreads();                   // tiles visible to all warps
            aHi = sb + SM_A;
            aLo = aHi + 16384u;
        } else {
            aHi = sb + SM_H + (uint32_t)(ph - 6) * 32768u;
            aLo = aHi + 16384u;
        }

        const uint32_t bHi = sb + SM_B + (uint32_t)buf * 32768u + (uint32_t)warp_n * 8192u;
        compute_chunk(acc, aHi, aLo, bHi, bHi + 16384u, lane, warpMrow);

        if (ph == 3) {
            // Epilogue A: bias + leaky -> H tiles (bf16 hi/lo, SW128), reset acc.
            // H reads happen at ph>=6 compute, behind later barriers.
#pragma unroll
            for (int mt = 0; mt < 2; mt++)
#pragma unroll
                for (int nt = 0; nt < 8; nt++) {
                    int col = warp_n * 64 + nt * 8 + 2 * tig;
                    int hc = col >> 6, kk = col & 63;
                    float bb0 = b_lin[col], bb1 = b_lin[col + 1];
                    unsigned char* hbase = (unsigned char*)smem + SM_H + hc * 32768;
#pragma unroll
                    for (int rr = 0; rr < 2; rr++) {
                        int r = warpMrow + mt * 16 + gid + rr * 8;
                        float v0 = acc[mt][nt][rr * 2]     + bb0;
                        float v1 = acc[mt][nt][rr * 2 + 1] + bb1;
                        v0 = (v0 >= 0.f) ? v0 : 0.1f * v0;
                        v1 = (v1 >= 0.f) ? v1 : 0.1f * v1;
                        uint32_t sw = SWZ((uint32_t)r * 128u + (uint32_t)kk * 2u);
                        uint32_t lo;
                        uint32_t hi = split2(v0, v1, lo);
                        *(uint32_t*)(hbase + sw)         = hi;
                        *(uint32_t*)(hbase + 16384 + sw) = lo;
                        acc[mt][nt][rr * 2]     = 0.f;
                        acc[mt][nt][rr * 2 + 1] = 0.f;
                    }
                }
        }
        __syncthreads();   // compute(ph) reads done before prefetch(ph+2) refills buf
    }

    // Epilogue B: bias + leaky -> out (fp32 pairs)
#pragma unroll
    for (int mt = 0; mt < 2; mt++)
#pragma unroll
        for (int nt = 0; nt < 8; nt++) {
            int col = warp_n * 64 + nt * 8 + 2 * tig;
            float bb0 = b_fus[col], bb1 = b_fus[col + 1];
#pragma unroll
            for (int rr = 0; rr < 2; rr++) {
                long long r = p0 + warpMrow + mt * 16 + gid + rr * 8;
                float v0 = acc[mt][nt][rr * 2]     + bb0;
                float v1 = acc[mt][nt][rr * 2 + 1] + bb1;
                v0 = (v0 >= 0.f) ? v0 : 0.1f * v0;
                v1 = (v1 >= 0.f) ? v1 : 0.1f * v1;
                *reinterpret_cast<float2*>(out + r * 128 + col) = make_float2(v0, v1);
            }
        }
}

// ------------------------------- launch -------------------------------------
extern "C" void kernel_launch(void* const* d_in, const int* in_sizes, int n_in,
                              void* d_out, int out_size)
{
    const float* x_down = (const float*)d_in[0];
    const float* x_up   = (const float*)d_in[1];
    const int*   up_idx = (const int*)d_in[2];      // int32 (JAX x64 off)
    const float* W_lin  = (const float*)d_in[3];
    const float* b_lin  = (const float*)d_in[4];
    const float* W_fus  = (const float*)d_in[5];
    const float* b_fus  = (const float*)d_in[6];
    float*       out    = (float*)d_out;

    const long long total_rows = in_sizes[2];                         // B * N_up
    const long long B          = (long long)in_sizes[0] / ((long long)N_DOWN * C_DOWN);
    const long long n_up_pb    = total_rows / B;

    cudaFuncSetAttribute(mlp_tc_kernel,
                         cudaFuncAttributeMaxDynamicSharedMemorySize, SMEM_TOTAL);

    pack_w<<<128, 256>>>(W_lin, W_fus);

    const int grid = (int)(total_rows / TMROWS);
    mlp_tc_kernel<<<grid, THREADS, SMEM_TOTAL>>>(x_down, x_up, up_idx,
                                                 b_lin, b_fus, out, n_up_pb);
}